// round 11
// baseline (speedup 1.0000x reference)
#include <cuda_runtime.h>
#include <stdint.h>
#include <cub/block/block_radix_sort.cuh>

#define B_   4
#define H_   8
#define N_   2048
#define DV_  64
#define BH_  (B_ * H_)            // 32
#define COLS_ (BH_ * DV_)         // 2048 sort columns
#define OUT_ELEMS (BH_ * (size_t)N_ * DV_)
#define ATTN_ELEMS ((size_t)BH_ * N_ * N_)

// ---------------- scratch ----------------------------------------------------
__device__ uint32_t g_key [COLS_ * N_];   // sortable v, [bh][d][i]
__device__ float    g_vs  [COLS_ * N_];   // sorted values [bh][d][r]
__device__ uint16_t g_inv [COLS_ * N_];   // rank of orig index i
__device__ uint16_t g_p0  [BH_  * N_];    // p_0[r]

__device__ __forceinline__ uint32_t f2sort(float x) {
    uint32_t u = __float_as_uint(x);
    return u ^ ((u & 0x80000000u) ? 0xFFFFFFFFu : 0x80000000u);
}
__device__ __forceinline__ float sort2f(uint32_t u) {
    u ^= (u & 0x80000000u) ? 0x80000000u : 0xFFFFFFFFu;
    return __uint_as_float(u);
}

// ---------------- 1) transpose v [bh][i][d] -> g_key [bh][d][i] --------------
__global__ void k_transpose_in(const float* __restrict__ v) {
    __shared__ float tile[32][33];
    int bh = blockIdx.z;
    int i0 = blockIdx.x * 32;
    int d0 = blockIdx.y * 32;
    int tx = threadIdx.x, ty = threadIdx.y;     // (32,8)
    const float* src = v + (size_t)bh * N_ * DV_;
#pragma unroll
    for (int r = 0; r < 32; r += 8)
        tile[ty + r][tx] = src[(size_t)(i0 + ty + r) * DV_ + (d0 + tx)];
    __syncthreads();
    uint32_t* dst = g_key + (size_t)bh * DV_ * N_;
#pragma unroll
    for (int r = 0; r < 32; r += 8)
        dst[(size_t)(d0 + ty + r) * N_ + (i0 + tx)] = f2sort(tile[tx][ty + r]);
}

// ---------------- 2) fused: CUB radix argsort + attn zero-fill ---------------
// One block per column. Stable LSD radix (CUB) on (key u32, idx u16):
// stability => ties keep ascending original index == jnp stable argsort.
// attn fill: 6 chunks issued before the sort, 10 after; cross-block wave
// staggering keeps DRAM write drain continuous.
using BRS = cub::BlockRadixSort<uint32_t, 256, 8, uint16_t>;

__global__ __launch_bounds__(256) void k_sortfill(float* __restrict__ attn) {
    const int col  = blockIdx.x;
    const int t    = threadIdx.x;
    const int ebase = t * 8;

    float4* __restrict__ fbase =
        reinterpret_cast<float4*>(attn) + (size_t)col * 16384 + t;
    const float4 z = make_float4(0.f, 0.f, 0.f, 0.f);
#define FILL4(c)                                                     \
    {  _Pragma("unroll")                                             \
       for (int s_ = 0; s_ < 4; s_++)                                \
           __stcs(fbase + (c) * 1024 + s_ * 256, z); }

    __shared__ typename BRS::TempStorage ts;

    const uint32_t* __restrict__ key = g_key + (size_t)col * N_;

    // pre-sort fill (6 chunks = 96KB)
    FILL4(0) FILL4(1) FILL4(2)

    uint32_t keys[8];
    uint16_t vals[8];
    {
        uint4 k0 = *reinterpret_cast<const uint4*>(key + ebase);
        uint4 k1 = *reinterpret_cast<const uint4*>(key + ebase + 4);
        keys[0] = k0.x; keys[1] = k0.y; keys[2] = k0.z; keys[3] = k0.w;
        keys[4] = k1.x; keys[5] = k1.y; keys[6] = k1.z; keys[7] = k1.w;
#pragma unroll
        for (int r = 0; r < 8; r++) vals[r] = (uint16_t)(ebase + r);
    }

    FILL4(3) FILL4(4) FILL4(5)

    BRS(ts).Sort(keys, vals);   // blocked: thread t holds ranks t*8..t*8+7

    // post-sort fill (10 chunks = 160KB)
    FILL4(6) FILL4(7) FILL4(8) FILL4(9) FILL4(10)

    // epilogue: rank e = ebase + r
    const int d  = col & 63;
    const int bh = col >> 6;
    float*    __restrict__ vs  = g_vs  + (size_t)col * N_;
    uint16_t* __restrict__ inv = g_inv + (size_t)col * N_;
    {
        float4 f0 = make_float4(sort2f(keys[0]), sort2f(keys[1]),
                                sort2f(keys[2]), sort2f(keys[3]));
        float4 f1 = make_float4(sort2f(keys[4]), sort2f(keys[5]),
                                sort2f(keys[6]), sort2f(keys[7]));
        *reinterpret_cast<float4*>(vs + ebase)     = f0;
        *reinterpret_cast<float4*>(vs + ebase + 4) = f1;
    }
#pragma unroll
    for (int r = 0; r < 8; r++) {
        inv[vals[r]] = (uint16_t)(ebase + r);
        if (d == 0) g_p0[bh * N_ + ebase + r] = vals[r];
    }

    FILL4(11) FILL4(12) FILL4(13) FILL4(14) FILL4(15)
#undef FILL4
}

// ---------------- 3) gather+transpose (and attn scatter blocks) --------------
__global__ __launch_bounds__(512) void k_gather_t(float* __restrict__ out,
                                                  float* __restrict__ attn) {
    if (blockIdx.y == BH_) {   // attn: attn[bh][i][ p0[inv1[i]] ] = 1
        int base = blockIdx.x * 4096;
        for (int m = threadIdx.x; m < 4096; m += 512) {
            int gid = base + m;
            int bh = gid >> 11;
            int i  = gid & (N_ - 1);
            int j    = g_inv[(size_t)(bh * DV_ + 1) * N_ + i];
            int aidx = g_p0[bh * N_ + j];
            attn[(size_t)gid * N_ + aidx] = 1.0f;
        }
        return;
    }
    const int bh = blockIdx.y;
    const int d0 = blockIdx.x * 4;
    const int t  = threadIdx.x;

    __shared__ float    svs [4 * N_];        // 32KB
    __shared__ uint16_t sinv[4][512 + 8];

#pragma unroll
    for (int d = 0; d < 4; d++)
        for (int i = t; i < N_; i += 512)
            svs[d * N_ + i] = g_vs[(size_t)(bh * DV_ + d0 + d) * N_ + i];

    const int dd = t & 3;
    const int iw = t >> 2;
    float* obase = out + (size_t)bh * N_ * DV_ + d0 + dd;

    for (int it = 0; it < 4; it++) {
        const int i0 = it * 512;
        __syncthreads();
#pragma unroll
        for (int d = 0; d < 4; d++) {
            int d1 = (d0 + d + 1) & 63;
            sinv[d][t] = g_inv[(size_t)(bh * DV_ + d1) * N_ + i0 + t];
        }
        __syncthreads();
#pragma unroll
        for (int rr = 0; rr < 4; rr++) {
            int ii = rr * 128 + iw;
            int rank = sinv[dd][ii];
            obase[(size_t)(i0 + ii) * DV_] = svs[dd * N_ + rank];
        }
    }
}

// ---------------- launch ------------------------------------------------------
extern "C" void kernel_launch(void* const* d_in, const int* in_sizes, int n_in,
                              void* d_out, int out_size) {
    (void)in_sizes; (void)n_in; (void)out_size;
    const float* v = (const float*)d_in[2];      // order: q, k, v
    float* out  = (float*)d_out;
    float* attn = out + OUT_ELEMS;

    k_transpose_in <<<dim3(N_ / 32, DV_ / 32, BH_), dim3(32, 8)>>>(v);
    k_sortfill     <<<COLS_, 256>>>(attn);
    k_gather_t     <<<dim3(16, BH_ + 1), 512>>>(out, attn);
}